// round 10
// baseline (speedup 1.0000x reference)
#include <cuda_runtime.h>
#include <cstdint>

#define M_TOK   8192
#define D_DIM   4096
#define F_DIM   16384
#define NCHUNK  128
#define F32_EPS 1.1920929e-07f

#define S8_P1 0x01u
#define S8_N1 0xFFu

__device__ __align__(16) uint8_t  g_Xq[(size_t)M_TOK * D_DIM];
__device__ __align__(16) uint8_t  g_Kq[(size_t)F_DIM * D_DIM];
__device__ __align__(16) uint32_t g_Xbits[NCHUNK * M_TOK];
__device__ __align__(16) uint32_t g_Kbits[NCHUNK * F_DIM];
__device__ float g_bx[M_TOK];
__device__ float g_bk[F_DIM];
__device__ float g_bkpart[32][F_DIM];

__device__ __forceinline__ uint32_t smem_u32(const void* p) {
    uint32_t a;
    asm("{ .reg .u64 t; cvta.to.shared.u64 t, %1; cvt.u32.u64 %0, t; }" : "=r"(a) : "l"(p));
    return a;
}
__device__ __forceinline__ uint32_t sw128(uint32_t off) { return off ^ ((off >> 3) & 0x70u); }
__device__ __forceinline__ void cp16(uint32_t dst, const void* src) {
    asm volatile("cp.async.cg.shared.global [%0], [%1], 16;" :: "r"(dst), "l"(src));
}
__device__ __forceinline__ void ldsm4(uint32_t& r0, uint32_t& r1, uint32_t& r2, uint32_t& r3,
                                      uint32_t addr) {
    asm volatile("ldmatrix.sync.aligned.m8n8.x4.shared.b16 {%0,%1,%2,%3}, [%4];"
                 : "=r"(r0), "=r"(r1), "=r"(r2), "=r"(r3) : "r"(addr));
}
__device__ __forceinline__ void mma_s8(int* c, uint32_t a0, uint32_t a1, uint32_t a2, uint32_t a3,
                                       uint32_t b0, uint32_t b1) {
    asm volatile("mma.sync.aligned.m16n8k32.row.col.s32.s8.s8.s32 "
                 "{%0,%1,%2,%3}, {%4,%5,%6,%7}, {%8,%9}, {%0,%1,%2,%3};"
                 : "+r"(c[0]), "+r"(c[1]), "+r"(c[2]), "+r"(c[3])
                 : "r"(a0), "r"(a1), "r"(a2), "r"(a3), "r"(b0), "r"(b1));
}
#define CP_COMMIT() asm volatile("cp.async.commit_group;" ::: "memory")
#define BAR_POPC()  asm volatile("bar.sync 1, 320;" ::: "memory")
#define BAR_TEN()   asm volatile("bar.sync 2, 192;" ::: "memory")

// ---------------------------------------------------------------------------
// Pack passes (validated in R6-R8)
// ---------------------------------------------------------------------------
__global__ void pack_x_s8_kernel(const float* __restrict__ x) {
    int token = blockIdx.x * (blockDim.x >> 5) + (threadIdx.x >> 5);
    int lane  = threadIdx.x & 31;
    const float4* row = (const float4*)(x + (size_t)token * D_DIM);
    uint8_t* qrow = g_Xq + (size_t)token * D_DIM;
    const int sh = (lane & 7) * 4;
    float m = 0.f;
    #pragma unroll 4
    for (int c = 0; c < 32; ++c) {
        float4 v = row[c * 32 + lane];
        m = fmaxf(m, fmaxf(fmaxf(fabsf(v.x), fabsf(v.y)), fmaxf(fabsf(v.z), fabsf(v.w))));
        uint32_t b = (v.x < 0.f ? S8_N1 : S8_P1)
                   | ((v.y < 0.f ? S8_N1 : S8_P1) << 8)
                   | ((v.z < 0.f ? S8_N1 : S8_P1) << 16)
                   | ((v.w < 0.f ? S8_N1 : S8_P1) << 24);
        *(uint32_t*)(qrow + c * 128 + lane * 4) = b;
        uint32_t nib = (v.x < 0.f ? 1u : 0u) | (v.y < 0.f ? 2u : 0u)
                     | (v.z < 0.f ? 4u : 0u) | (v.w < 0.f ? 8u : 0u);
        uint32_t w = nib << sh;
        w |= __shfl_xor_sync(0xffffffffu, w, 1);
        w |= __shfl_xor_sync(0xffffffffu, w, 2);
        w |= __shfl_xor_sync(0xffffffffu, w, 4);
        if ((lane & 7) == 0)
            g_Xbits[(c * 4 + (lane >> 3)) * M_TOK + token] = w;
    }
    #pragma unroll
    for (int o = 16; o; o >>= 1) m = fmaxf(m, __shfl_xor_sync(0xffffffffu, m, o));
    if (lane == 0) g_bx[token] = m + F32_EPS;
}

__global__ __launch_bounds__(256)
void pack_k_s8_kernel(const float* __restrict__ kern) {
    __shared__ uint8_t T[128 * 132];
    __shared__ float smax[128];
    const int tid = threadIdx.x;
    const int f0 = blockIdx.x * 128, d0 = blockIdx.y * 128;
    if (tid < 128) smax[tid] = 0.f;
    __syncthreads();

    const int fq = tid & 31;
    float m0 = 0.f, m1 = 0.f, m2 = 0.f, m3 = 0.f;
    #pragma unroll 4
    for (int i = 0; i < 16; ++i) {
        int dr = i * 8 + (tid >> 5);
        float4 v = *(const float4*)(kern + (size_t)(d0 + dr) * F_DIM + f0 + fq * 4);
        m0 = fmaxf(m0, fabsf(v.x)); m1 = fmaxf(m1, fabsf(v.y));
        m2 = fmaxf(m2, fabsf(v.z)); m3 = fmaxf(m3, fabsf(v.w));
        T[(fq * 4 + 0) * 132 + dr] = v.x < 0.f ? S8_N1 : S8_P1;
        T[(fq * 4 + 1) * 132 + dr] = v.y < 0.f ? S8_N1 : S8_P1;
        T[(fq * 4 + 2) * 132 + dr] = v.z < 0.f ? S8_N1 : S8_P1;
        T[(fq * 4 + 3) * 132 + dr] = v.w < 0.f ? S8_N1 : S8_P1;
    }
    atomicMax((int*)&smax[fq * 4 + 0], __float_as_int(m0));
    atomicMax((int*)&smax[fq * 4 + 1], __float_as_int(m1));
    atomicMax((int*)&smax[fq * 4 + 2], __float_as_int(m2));
    atomicMax((int*)&smax[fq * 4 + 3], __float_as_int(m3));
    __syncthreads();

    const int lane = tid & 31;
    const int sh = (lane & 7) * 4;
    const int cbase = (d0 >> 5) + (lane >> 3);
    #pragma unroll 4
    for (int i = 0; i < 16; ++i) {
        int idx = i * 256 + tid;
        int fr = idx >> 5;
        uint32_t w = *(uint32_t*)&T[fr * 132 + lane * 4];
        *(uint32_t*)(g_Kq + (size_t)(f0 + fr) * D_DIM + d0 + lane * 4) = w;
        uint32_t nib = ((w >> 7) & 1u) | ((w >> 14) & 2u)
                     | ((w >> 21) & 4u) | ((w >> 28) & 8u);
        uint32_t bw = nib << sh;
        bw |= __shfl_xor_sync(0xffffffffu, bw, 1);
        bw |= __shfl_xor_sync(0xffffffffu, bw, 2);
        bw |= __shfl_xor_sync(0xffffffffu, bw, 4);
        if ((lane & 7) == 0)
            g_Kbits[(size_t)cbase * F_DIM + f0 + fr] = bw;
    }
    if (tid < 128) g_bkpart[blockIdx.y][f0 + tid] = smax[tid];
}

__global__ void reduce_bk_kernel() {
    int f = blockIdx.x * blockDim.x + threadIdx.x;
    float m = 0.f;
    #pragma unroll
    for (int s = 0; s < 32; ++s) m = fmaxf(m, g_bkpart[s][f]);
    g_bk[f] = m + F32_EPS;
}

// ---------------------------------------------------------------------------
// 3-way pipe-split GEMM. 512 threads per 128x128 tile, k-step 256B.
//   warps 0-3  : s8 mma,  cols [80,112)   tensor pipe
//   warps 4-5  : dp4a,    cols [112,128)  fma pipe
//   warps 6-15 : XOR+POPC cols [0,80)     alu pipe
// popc: 3 stages, prefetch distance 2, DOUBLE barrier per iter (post-compute
// barrier makes writing stage (kt-1)%3 safe -- fixes the R9 race).
// ---------------------------------------------------------------------------
#define STG_I   45056
#define OFF_B   32768
#define POPC_0  90112
#define STG_P   6656
#define SMEM_SZ 110080

__global__ __launch_bounds__(512, 2)
void hybrid3_gemm(const float* __restrict__ bias, float* __restrict__ out) {
    extern __shared__ uint8_t smem[];
    const uint32_t sb = smem_u32(smem);
    const int tid = threadIdx.x, wid = tid >> 5, lane = tid & 31;
    const int f0 = blockIdx.x * 128;
    const int t0 = blockIdx.y * 128;

    if (wid >= 6) {
        // ============ popcount group: warps 6..15, cols [0,80) ============
        const int pt = tid - 192;                    // 0..319
        auto fillP = [&](int kt, int st) {
            const uint32_t base = sb + POPC_0 + st * STG_P;
            if (pt < 256) {
                int ch = pt >> 5, q = pt & 31;
                cp16(base + ch * 512 + q * 16,
                     g_Xbits + (size_t)(kt * 8 + ch) * M_TOK + t0 + q * 4);
            }
            if (pt < 160) {
                int ch = pt / 20, q = pt % 20;
                cp16(base + 4096 + ch * 320 + q * 16,
                     g_Kbits + (size_t)(kt * 8 + ch) * F_DIM + f0 + q * 4);
            }
            CP_COMMIT();
        };

        const int pw = wid - 6;                      // 0..9
        const int wm = pw & 1, wn = pw >> 1;         // 2m x 5n, warp tile 64x16
        const int r0 = wm * 64 + (lane >> 2) * 8;
        const int c0 = wn * 16 + (lane & 3) * 4;
        int acc[8][4];
        #pragma unroll
        for (int i = 0; i < 8; ++i)
            #pragma unroll
            for (int j = 0; j < 4; ++j) acc[i][j] = 0;

        fillP(0, 0);
        fillP(1, 1);
        for (int kt = 0; kt < 16; ++kt) {
            if (kt + 2 < 16) fillP(kt + 2, (kt + 2) % 3); else CP_COMMIT();
            asm volatile("cp.async.wait_group 2;" ::: "memory");
            BAR_POPC();
            const uint8_t* base = smem + POPC_0 + (kt % 3) * STG_P;
            #pragma unroll
            for (int c = 0; c < 8; c += 2) {
                uint32_t xa0[8], kb0[4], xa1[8], kb1[4];
                *(uint4*)&xa0[0] = *(const uint4*)(base + c * 512 + r0 * 4);
                *(uint4*)&xa0[4] = *(const uint4*)(base + c * 512 + r0 * 4 + 16);
                *(uint4*)&kb0[0] = *(const uint4*)(base + 4096 + c * 320 + c0 * 4);
                *(uint4*)&xa1[0] = *(const uint4*)(base + (c + 1) * 512 + r0 * 4);
                *(uint4*)&xa1[4] = *(const uint4*)(base + (c + 1) * 512 + r0 * 4 + 16);
                *(uint4*)&kb1[0] = *(const uint4*)(base + 4096 + (c + 1) * 320 + c0 * 4);
                #pragma unroll
                for (int i = 0; i < 8; ++i)
                    #pragma unroll
                    for (int j = 0; j < 4; ++j)
                        acc[i][j] += __popc(xa0[i] ^ kb0[j]) + __popc(xa1[i] ^ kb1[j]);
            }
            BAR_POPC();   // write-after-read guard for 3-stage/dist-2 schedule
        }

        const int trow = t0 + r0, tcol = f0 + c0;
        float bk4[4], bs4[4];
        #pragma unroll
        for (int j = 0; j < 4; ++j) { bk4[j] = g_bk[tcol + j]; bs4[j] = bias[tcol + j]; }
        #pragma unroll
        for (int i = 0; i < 8; ++i) {
            float sx = 0.25f * g_bx[trow + i];
            float4 r;
            r.x = fmaf(sx * bk4[0], (float)(D_DIM - 2 * acc[i][0]), bs4[0]);
            r.y = fmaf(sx * bk4[1], (float)(D_DIM - 2 * acc[i][1]), bs4[1]);
            r.z = fmaf(sx * bk4[2], (float)(D_DIM - 2 * acc[i][2]), bs4[2]);
            r.w = fmaf(sx * bk4[3], (float)(D_DIM - 2 * acc[i][3]), bs4[3]);
            *(float4*)(out + (size_t)(trow + i) * F_DIM + tcol) = r;
        }
        return;
    }

    // ============ tensor group: warps 0..5 (imma 0-3, dp4a 4-5) ============
    const int t = tid;                               // 0..191
    const uint8_t* __restrict__ gA  = g_Xq + (size_t)t0 * D_DIM;
    const uint8_t* __restrict__ gB  = g_Kq + (size_t)(f0 + 80) * D_DIM;  // 48 rows

    auto fillI = [&](int kt, int st) {
        const uint32_t base = sb + st * STG_I;
        const size_t gk = (size_t)kt * 256;
        #pragma unroll
        for (int i = 0; i < 11; ++i) {
            int idx = i * 192 + t;
            if (idx < 2048) {
                int sub = idx >> 10, r = (idx >> 3) & 127, c = (idx & 7) << 4;
                cp16(base + sub * 16384 + sw128(r * 128 + c),
                     gA + (size_t)r * D_DIM + gk + sub * 128 + c);
            }
        }
        #pragma unroll
        for (int i = 0; i < 4; ++i) {
            int idx = i * 192 + t;                   // 0..767
            int sub = idx / 384, rr = (idx >> 3) % 48, c = (idx & 7) << 4;
            cp16(base + OFF_B + sub * 6144 + sw128(rr * 128 + c),
                 gB + (size_t)rr * D_DIM + gk + sub * 128 + c);
        }
        CP_COMMIT();
    };

    if (wid < 4) {
        // -------- imma: cols [80,112) --------
        const int wm = wid & 1, wn = wid >> 1;       // 2m x 2n, warp tile 64x16
        int acc[4][2][4];
        #pragma unroll
        for (int mi = 0; mi < 4; ++mi)
            #pragma unroll
            for (int ni = 0; ni < 2; ++ni)
                #pragma unroll
                for (int r = 0; r < 4; ++r) acc[mi][ni][r] = 0;

        const int arow = wm * 64 + (lane & 15);
        const int brow = wn * 16 + (lane & 15);
        const int khalf = (lane & 16);

        fillI(0, 0);
        for (int kt = 0; kt < 16; ++kt) {
            if (kt < 15) {
                fillI(kt + 1, (kt + 1) & 1);
                asm volatile("cp.async.wait_group 1;" ::: "memory");
            } else {
                asm volatile("cp.async.wait_group 0;" ::: "memory");
            }
            BAR_TEN();
            const uint32_t stb = sb + (kt & 1) * STG_I;
            #pragma unroll
            for (int ks = 0; ks < 8; ++ks) {
                const int sub = ks >> 2;
                const int kcol = (ks & 3) * 32 + khalf;
                const uint32_t aSt = stb + sub * 16384;
                const uint32_t bSt = stb + OFF_B + sub * 6144;
                uint32_t b0, b1, b2, b3;
                ldsm4(b0, b1, b2, b3, bSt + sw128(brow * 128 + kcol));
                #pragma unroll
                for (int mi = 0; mi < 4; ++mi) {
                    uint32_t a0, a1, a2, a3;
                    ldsm4(a0, a1, a2, a3, aSt + sw128((arow + mi * 16) * 128 + kcol));
                    mma_s8(acc[mi][0], a0, a1, a2, a3, b0, b2);
                    mma_s8(acc[mi][1], a0, a1, a2, a3, b1, b3);
                }
            }
            BAR_TEN();
        }

        const int lrow = lane >> 2;
        const int lcol = (lane & 3) * 2;
        const int rbase = t0 + wm * 64;
        const int cbase = f0 + 80 + wn * 16;
        #pragma unroll
        for (int mi = 0; mi < 4; ++mi) {
            float sx0 = 0.25f * g_bx[rbase + mi * 16 + lrow];
            float sx1 = 0.25f * g_bx[rbase + mi * 16 + lrow + 8];
            #pragma unroll
            for (int ni = 0; ni < 2; ++ni) {
                int c = cbase + ni * 8 + lcol;
                float k0v = g_bk[c], k1v = g_bk[c + 1];
                float b0v = bias[c], b1v = bias[c + 1];
                float2 v0, v1;
                v0.x = fmaf(sx0 * k0v, (float)acc[mi][ni][0], b0v);
                v0.y = fmaf(sx0 * k1v, (float)acc[mi][ni][1], b1v);
                v1.x = fmaf(sx1 * k0v, (float)acc[mi][ni][2], b0v);
                v1.y = fmaf(sx1 * k1v, (float)acc[mi][ni][3], b1v);
                *(float2*)(out + (size_t)(rbase + mi * 16 + lrow) * F_DIM + c) = v0;
                *(float2*)(out + (size_t)(rbase + mi * 16 + lrow + 8) * F_DIM + c) = v1;
            }
        }
    } else {
        // -------- dp4a: warps 4-5, cols [112,128) --------
        const int wm = wid - 4;                      // 0..1, warp tile 64x16
        const int r0 = wm * 64 + (lane >> 2) * 8;
        const int cb = 32 + (lane & 3) * 4;          // B-tile rows 32..47
        int acc[8][4];
        #pragma unroll
        for (int i = 0; i < 8; ++i)
            #pragma unroll
            for (int j = 0; j < 4; ++j) acc[i][j] = 0;

        fillI(0, 0);
        for (int kt = 0; kt < 16; ++kt) {
            if (kt < 15) {
                fillI(kt + 1, (kt + 1) & 1);
                asm volatile("cp.async.wait_group 1;" ::: "memory");
            } else {
                asm volatile("cp.async.wait_group 0;" ::: "memory");
            }
            BAR_TEN();
            const uint8_t* stp = smem + (kt & 1) * STG_I;
            #pragma unroll
            for (int sub = 0; sub < 2; ++sub) {
                const uint8_t* aS = stp + sub * 16384;
                const uint8_t* bS = stp + OFF_B + sub * 6144;
                #pragma unroll
                for (int g = 0; g < 16; ++g) {
                    uint2 xa[8], kb[4];
                    #pragma unroll
                    for (int i = 0; i < 8; ++i)
                        xa[i] = *(const uint2*)(aS + sw128((r0 + i) * 128 + g * 8));
                    #pragma unroll
                    for (int j = 0; j < 4; ++j)
                        kb[j] = *(const uint2*)(bS + sw128((cb + j) * 128 + g * 8));
                    #pragma unroll
                    for (int i = 0; i < 8; ++i)
                        #pragma unroll
                        for (int j = 0; j < 4; ++j) {
                            acc[i][j] = __dp4a((int)xa[i].x, (int)kb[j].x, acc[i][j]);
                            acc[i][j] = __dp4a((int)xa[i].y, (int)kb[j].y, acc[i][j]);
                        }
                }
            }
            BAR_TEN();
        }

        const int trow = t0 + r0;
        const int tcol = f0 + 112 + (lane & 3) * 4;
        float bk4[4], bs4[4];
        #pragma unroll
        for (int j = 0; j < 4; ++j) { bk4[j] = g_bk[tcol + j]; bs4[j] = bias[tcol + j]; }
        #pragma unroll
        for (int i = 0; i < 8; ++i) {
            float sx = 0.25f * g_bx[trow + i];
            float4 r;
            r.x = fmaf(sx * bk4[0], (float)acc[i][0], bs4[0]);
            r.y = fmaf(sx * bk4[1], (float)acc[i][1], bs4[1]);
            r.z = fmaf(sx * bk4[2], (float)acc[i][2], bs4[2]);
            r.w = fmaf(sx * bk4[3], (float)acc[i][3], bs4[3]);
            *(float4*)(out + (size_t)(trow + i) * F_DIM + tcol) = r;
        }
    }
}

// ---------------------------------------------------------------------------
extern "C" void kernel_launch(void* const* d_in, const int* in_sizes, int n_in,
                              void* d_out, int out_size) {
    const float* x    = (const float*)d_in[0];
    const float* kern = (const float*)d_in[1];
    const float* bias = (const float*)d_in[2];
    float* out = (float*)d_out;

    pack_x_s8_kernel<<<M_TOK / 8, 256>>>(x);
    dim3 gk(F_DIM / 128, D_DIM / 128);
    pack_k_s8_kernel<<<gk, 256>>>(kern);
    reduce_bk_kernel<<<F_DIM / 256, 256>>>();

    cudaFuncSetAttribute(hybrid3_gemm,
                         cudaFuncAttributeMaxDynamicSharedMemorySize, SMEM_SZ);
    dim3 gg(F_DIM / 128, M_TOK / 128);
    hybrid3_gemm<<<gg, 512, SMEM_SZ>>>(bias, out);
}

// round 11
// speedup vs baseline: 2.0416x; 2.0416x over previous
#include <cuda_runtime.h>
#include <cstdint>

#define M_TOK   8192
#define D_DIM   4096
#define F_DIM   16384
#define NCHUNK  128
#define F32_EPS 1.1920929e-07f

#define S8_P1 0x01u
#define S8_N1 0xFFu

__device__ __align__(16) uint8_t  g_Xq[(size_t)M_TOK * D_DIM];
__device__ __align__(16) uint8_t  g_Kq[(size_t)F_DIM * D_DIM];
__device__ __align__(16) uint32_t g_Xbits[NCHUNK * M_TOK];
__device__ __align__(16) uint32_t g_Kbits[NCHUNK * F_DIM];
__device__ float g_bx[M_TOK];
__device__ float g_bk[F_DIM];
__device__ float g_bkpart[32][F_DIM];

__device__ __forceinline__ uint32_t smem_u32(const void* p) {
    uint32_t a;
    asm("{ .reg .u64 t; cvta.to.shared.u64 t, %1; cvt.u32.u64 %0, t; }" : "=r"(a) : "l"(p));
    return a;
}
__device__ __forceinline__ uint32_t sw128(uint32_t off) { return off ^ ((off >> 3) & 0x70u); }
__device__ __forceinline__ void cp16(uint32_t dst, const void* src) {
    asm volatile("cp.async.cg.shared.global [%0], [%1], 16;" :: "r"(dst), "l"(src));
}
__device__ __forceinline__ void ldsm4(uint32_t& r0, uint32_t& r1, uint32_t& r2, uint32_t& r3,
                                      uint32_t addr) {
    asm volatile("ldmatrix.sync.aligned.m8n8.x4.shared.b16 {%0,%1,%2,%3}, [%4];"
                 : "=r"(r0), "=r"(r1), "=r"(r2), "=r"(r3) : "r"(addr));
}
__device__ __forceinline__ void mma_s8(int* c, uint32_t a0, uint32_t a1, uint32_t a2, uint32_t a3,
                                       uint32_t b0, uint32_t b1) {
    asm volatile("mma.sync.aligned.m16n8k32.row.col.s32.s8.s8.s32 "
                 "{%0,%1,%2,%3}, {%4,%5,%6,%7}, {%8,%9}, {%0,%1,%2,%3};"
                 : "+r"(c[0]), "+r"(c[1]), "+r"(c[2]), "+r"(c[3])
                 : "r"(a0), "r"(a1), "r"(a2), "r"(a3), "r"(b0), "r"(b1));
}
#define CP_COMMIT() asm volatile("cp.async.commit_group;" ::: "memory")
#define BAR_POPC()  asm volatile("bar.sync 1, 384;" ::: "memory")
#define BAR_IMMA()  asm volatile("bar.sync 2, 128;" ::: "memory")

// ---------------------------------------------------------------------------
// Pack passes (validated R6-R8)
// ---------------------------------------------------------------------------
__global__ void pack_x_s8_kernel(const float* __restrict__ x) {
    int token = blockIdx.x * (blockDim.x >> 5) + (threadIdx.x >> 5);
    int lane  = threadIdx.x & 31;
    const float4* row = (const float4*)(x + (size_t)token * D_DIM);
    uint8_t* qrow = g_Xq + (size_t)token * D_DIM;
    const int sh = (lane & 7) * 4;
    float m = 0.f;
    #pragma unroll 4
    for (int c = 0; c < 32; ++c) {
        float4 v = row[c * 32 + lane];
        m = fmaxf(m, fmaxf(fmaxf(fabsf(v.x), fabsf(v.y)), fmaxf(fabsf(v.z), fabsf(v.w))));
        uint32_t b = (v.x < 0.f ? S8_N1 : S8_P1)
                   | ((v.y < 0.f ? S8_N1 : S8_P1) << 8)
                   | ((v.z < 0.f ? S8_N1 : S8_P1) << 16)
                   | ((v.w < 0.f ? S8_N1 : S8_P1) << 24);
        *(uint32_t*)(qrow + c * 128 + lane * 4) = b;
        uint32_t nib = (v.x < 0.f ? 1u : 0u) | (v.y < 0.f ? 2u : 0u)
                     | (v.z < 0.f ? 4u : 0u) | (v.w < 0.f ? 8u : 0u);
        uint32_t w = nib << sh;
        w |= __shfl_xor_sync(0xffffffffu, w, 1);
        w |= __shfl_xor_sync(0xffffffffu, w, 2);
        w |= __shfl_xor_sync(0xffffffffu, w, 4);
        if ((lane & 7) == 0)
            g_Xbits[(c * 4 + (lane >> 3)) * M_TOK + token] = w;
    }
    #pragma unroll
    for (int o = 16; o; o >>= 1) m = fmaxf(m, __shfl_xor_sync(0xffffffffu, m, o));
    if (lane == 0) g_bx[token] = m + F32_EPS;
}

__global__ __launch_bounds__(256)
void pack_k_s8_kernel(const float* __restrict__ kern) {
    __shared__ uint8_t T[128 * 132];
    __shared__ float smax[128];
    const int tid = threadIdx.x;
    const int f0 = blockIdx.x * 128, d0 = blockIdx.y * 128;
    if (tid < 128) smax[tid] = 0.f;
    __syncthreads();

    const int fq = tid & 31;
    float m0 = 0.f, m1 = 0.f, m2 = 0.f, m3 = 0.f;
    #pragma unroll 4
    for (int i = 0; i < 16; ++i) {
        int dr = i * 8 + (tid >> 5);
        float4 v = *(const float4*)(kern + (size_t)(d0 + dr) * F_DIM + f0 + fq * 4);
        m0 = fmaxf(m0, fabsf(v.x)); m1 = fmaxf(m1, fabsf(v.y));
        m2 = fmaxf(m2, fabsf(v.z)); m3 = fmaxf(m3, fabsf(v.w));
        T[(fq * 4 + 0) * 132 + dr] = v.x < 0.f ? S8_N1 : S8_P1;
        T[(fq * 4 + 1) * 132 + dr] = v.y < 0.f ? S8_N1 : S8_P1;
        T[(fq * 4 + 2) * 132 + dr] = v.z < 0.f ? S8_N1 : S8_P1;
        T[(fq * 4 + 3) * 132 + dr] = v.w < 0.f ? S8_N1 : S8_P1;
    }
    atomicMax((int*)&smax[fq * 4 + 0], __float_as_int(m0));
    atomicMax((int*)&smax[fq * 4 + 1], __float_as_int(m1));
    atomicMax((int*)&smax[fq * 4 + 2], __float_as_int(m2));
    atomicMax((int*)&smax[fq * 4 + 3], __float_as_int(m3));
    __syncthreads();

    const int lane = tid & 31;
    const int sh = (lane & 7) * 4;
    const int cbase = (d0 >> 5) + (lane >> 3);
    #pragma unroll 4
    for (int i = 0; i < 16; ++i) {
        int idx = i * 256 + tid;
        int fr = idx >> 5;
        uint32_t w = *(uint32_t*)&T[fr * 132 + lane * 4];
        *(uint32_t*)(g_Kq + (size_t)(f0 + fr) * D_DIM + d0 + lane * 4) = w;
        uint32_t nib = ((w >> 7) & 1u) | ((w >> 14) & 2u)
                     | ((w >> 21) & 4u) | ((w >> 28) & 8u);
        uint32_t bw = nib << sh;
        bw |= __shfl_xor_sync(0xffffffffu, bw, 1);
        bw |= __shfl_xor_sync(0xffffffffu, bw, 2);
        bw |= __shfl_xor_sync(0xffffffffu, bw, 4);
        if ((lane & 7) == 0)
            g_Kbits[(size_t)cbase * F_DIM + f0 + fr] = bw;
    }
    if (tid < 128) g_bkpart[blockIdx.y][f0 + tid] = smax[tid];
}

__global__ void reduce_bk_kernel() {
    int f = blockIdx.x * blockDim.x + threadIdx.x;
    float m = 0.f;
    #pragma unroll
    for (int s = 0; s < 32; ++s) m = fmaxf(m, g_bkpart[s][f]);
    g_bk[f] = m + F32_EPS;
}

// ---------------------------------------------------------------------------
// Decoupled warp-split hybrid GEMM (R7 architecture).
//   warps 0-11 (384t): XOR+POPC cols [0,96), 512B k-step, 2 stages,
//                      double-barrier (race-free), bar.sync 1
//   warps 12-15(128t): s8 mma   cols [96,128), 256B k-step, 2 stages, bar 2
// Smem: imma stages 2 x 40960 @0; popc stages 2 x 14336 @81920. Total 110592.
// popc stage: X 16x512B @0 | K 16x384B @8192
// ---------------------------------------------------------------------------
#define STG_I   40960
#define OFF_B   32768
#define POPC_0  81920
#define STG_P   14336
#define SMEM_SZ 110592

__global__ __launch_bounds__(512, 2)
void hybrid_dc_gemm(const float* __restrict__ bias, float* __restrict__ out) {
    extern __shared__ uint8_t smem[];
    const uint32_t sb = smem_u32(smem);
    const int tid = threadIdx.x, wid = tid >> 5, lane = tid & 31;
    const int f0 = blockIdx.x * 128;
    const int t0 = blockIdx.y * 128;

    if (wid < 12) {
        // ============ popcount group: warps 0..11, cols [0,96) ============
        const int pt = tid;                          // 0..383
        auto fillP = [&](int kt, int st) {
            const uint32_t base = sb + POPC_0 + st * STG_P;
            {   // X: 512 cp16 (16 chunks x 128 tokens x 4B)
                int ch = pt >> 5, q = pt & 31;
                cp16(base + ch * 512 + q * 16,
                     g_Xbits + (size_t)(kt * 16 + ch) * M_TOK + t0 + q * 4);
                if (pt < 128) {
                    int ch2 = (pt + 384) >> 5, q2 = (pt + 384) & 31;
                    cp16(base + ch2 * 512 + q2 * 16,
                         g_Xbits + (size_t)(kt * 16 + ch2) * M_TOK + t0 + q2 * 4);
                }
            }
            {   // K: 384 cp16 (16 chunks x 96 feats x 4B)
                int ch = pt / 24, q = pt % 24;
                cp16(base + 8192 + ch * 384 + q * 16,
                     g_Kbits + (size_t)(kt * 16 + ch) * F_DIM + f0 + q * 4);
            }
            CP_COMMIT();
        };

        const int pm = wid & 3, pn = wid >> 2;       // 4m x 3n warp grid
        const int r0 = pm * 32 + (lane >> 3) * 8;
        const int c0 = pn * 32 + (lane & 7) * 4;
        int acc[8][4];
        #pragma unroll
        for (int i = 0; i < 8; ++i)
            #pragma unroll
            for (int j = 0; j < 4; ++j) acc[i][j] = 0;

        fillP(0, 0);
        fillP(1, 1);
        for (int kt = 0; kt < 8; ++kt) {
            if (kt < 7) {
                asm volatile("cp.async.wait_group 1;" ::: "memory");
            } else {
                asm volatile("cp.async.wait_group 0;" ::: "memory");
            }
            BAR_POPC();                              // data visible to all
            const uint8_t* base = smem + POPC_0 + (kt & 1) * STG_P;
            #pragma unroll
            for (int c = 0; c < 16; c += 2) {
                uint32_t xa0[8], kb0[4], xa1[8], kb1[4];
                *(uint4*)&xa0[0] = *(const uint4*)(base + c * 512 + r0 * 4);
                *(uint4*)&xa0[4] = *(const uint4*)(base + c * 512 + r0 * 4 + 16);
                *(uint4*)&kb0[0] = *(const uint4*)(base + 8192 + c * 384 + c0 * 4);
                *(uint4*)&xa1[0] = *(const uint4*)(base + (c + 1) * 512 + r0 * 4);
                *(uint4*)&xa1[4] = *(const uint4*)(base + (c + 1) * 512 + r0 * 4 + 16);
                *(uint4*)&kb1[0] = *(const uint4*)(base + 8192 + (c + 1) * 384 + c0 * 4);
                #pragma unroll
                for (int i = 0; i < 8; ++i)
                    #pragma unroll
                    for (int j = 0; j < 4; ++j)
                        acc[i][j] += __popc(xa0[i] ^ kb0[j]) + __popc(xa1[i] ^ kb1[j]);
            }
            BAR_POPC();                              // all reads of stage kt&1 done
            if (kt + 2 < 8) fillP(kt + 2, (kt + 2) & 1);   // safe: post-barrier
        }

        const int trow = t0 + r0, tcol = f0 + c0;
        float bk4[4], bs4[4];
        #pragma unroll
        for (int j = 0; j < 4; ++j) { bk4[j] = g_bk[tcol + j]; bs4[j] = bias[tcol + j]; }
        #pragma unroll
        for (int i = 0; i < 8; ++i) {
            float sx = 0.25f * g_bx[trow + i];
            float4 r;
            r.x = fmaf(sx * bk4[0], (float)(D_DIM - 2 * acc[i][0]), bs4[0]);
            r.y = fmaf(sx * bk4[1], (float)(D_DIM - 2 * acc[i][1]), bs4[1]);
            r.z = fmaf(sx * bk4[2], (float)(D_DIM - 2 * acc[i][2]), bs4[2]);
            r.w = fmaf(sx * bk4[3], (float)(D_DIM - 2 * acc[i][3]), bs4[3]);
            *(float4*)(out + (size_t)(trow + i) * F_DIM + tcol) = r;
        }
    } else {
        // ============ imma group: warps 12..15, cols [96,128) ============
        const int t = tid - 384;                     // 0..127
        const uint8_t* __restrict__ gA  = g_Xq + (size_t)t0 * D_DIM;
        const uint8_t* __restrict__ gBq = g_Kq + (size_t)(f0 + 96) * D_DIM;

        auto fillI = [&](int kt, int st) {
            const uint32_t base = sb + st * STG_I;
            const size_t gk = (size_t)kt * 256;
            #pragma unroll
            for (int i = 0; i < 16; ++i) {
                int idx = i * 128 + t;
                int sub = idx >> 10, r = (idx >> 3) & 127, c = (idx & 7) << 4;
                cp16(base + sub * 16384 + sw128(r * 128 + c),
                     gA + (size_t)r * D_DIM + gk + sub * 128 + c);
            }
            #pragma unroll
            for (int i = 0; i < 4; ++i) {
                int idx = i * 128 + t;
                int sub = idx >> 8, r = (idx >> 3) & 31, c = (idx & 7) << 4;
                cp16(base + OFF_B + sub * 4096 + sw128(r * 128 + c),
                     gBq + (size_t)r * D_DIM + gk + sub * 128 + c);
            }
            CP_COMMIT();
        };

        const int iw = wid - 12;
        const int wm = iw & 1, wn = iw >> 1;         // 2m x 2n, warp tile 64x16
        int acc[4][2][4];
        #pragma unroll
        for (int mi = 0; mi < 4; ++mi)
            #pragma unroll
            for (int ni = 0; ni < 2; ++ni)
                #pragma unroll
                for (int r = 0; r < 4; ++r) acc[mi][ni][r] = 0;

        const int arow = wm * 64 + (lane & 15);
        const int brow = wn * 16 + (lane & 15);
        const int khalf = (lane & 16);

        fillI(0, 0);
        for (int kt = 0; kt < 16; ++kt) {
            if (kt < 15) {
                fillI(kt + 1, (kt + 1) & 1);
                asm volatile("cp.async.wait_group 1;" ::: "memory");
            } else {
                asm volatile("cp.async.wait_group 0;" ::: "memory");
            }
            BAR_IMMA();
            const uint32_t stb = sb + (kt & 1) * STG_I;
            #pragma unroll
            for (int ks = 0; ks < 8; ++ks) {
                const int sub = ks >> 2;
                const int kcol = (ks & 3) * 32 + khalf;
                const uint32_t aSt = stb + sub * 16384;
                const uint32_t bSt = stb + OFF_B + sub * 4096;
                uint32_t b0, b1, b2, b3;
                ldsm4(b0, b1, b2, b3, bSt + sw128(brow * 128 + kcol));
                #pragma unroll
                for (int mi = 0; mi < 4; ++mi) {
                    uint32_t a0, a1, a2, a3;
                    ldsm4(a0, a1, a2, a3, aSt + sw128((arow + mi * 16) * 128 + kcol));
                    mma_s8(acc[mi][0], a0, a1, a2, a3, b0, b2);
                    mma_s8(acc[mi][1], a0, a1, a2, a3, b1, b3);
                }
            }
            BAR_IMMA();
        }

        const int lrow = lane >> 2;
        const int lcol = (lane & 3) * 2;
        const int rbase = t0 + wm * 64;
        const int cbase = f0 + 96 + wn * 16;
        #pragma unroll
        for (int mi = 0; mi < 4; ++mi) {
            float sx0 = 0.25f * g_bx[rbase + mi * 16 + lrow];
            float sx1 = 0.25f * g_bx[rbase + mi * 16 + lrow + 8];
            #pragma unroll
            for (int ni = 0; ni < 2; ++ni) {
                int c = cbase + ni * 8 + lcol;
                float k0v = g_bk[c], k1v = g_bk[c + 1];
                float b0v = bias[c], b1v = bias[c + 1];
                float2 v0, v1;
                v0.x = fmaf(sx0 * k0v, (float)acc[mi][ni][0], b0v);
                v0.y = fmaf(sx0 * k1v, (float)acc[mi][ni][1], b1v);
                v1.x = fmaf(sx1 * k0v, (float)acc[mi][ni][2], b0v);
                v1.y = fmaf(sx1 * k1v, (float)acc[mi][ni][3], b1v);
                *(float2*)(out + (size_t)(rbase + mi * 16 + lrow) * F_DIM + c) = v0;
                *(float2*)(out + (size_t)(rbase + mi * 16 + lrow + 8) * F_DIM + c) = v1;
            }
        }
    }
}

// ---------------------------------------------------------------------------
extern "C" void kernel_launch(void* const* d_in, const int* in_sizes, int n_in,
                              void* d_out, int out_size) {
    const float* x    = (const float*)d_in[0];
    const float* kern = (const float*)d_in[1];
    const float* bias = (const float*)d_in[2];
    float* out = (float*)d_out;

    pack_x_s8_kernel<<<M_TOK / 8, 256>>>(x);
    dim3 gk(F_DIM / 128, D_DIM / 128);
    pack_k_s8_kernel<<<gk, 256>>>(kern);
    reduce_bk_kernel<<<F_DIM / 256, 256>>>();

    cudaFuncSetAttribute(hybrid_dc_gemm,
                         cudaFuncAttributeMaxDynamicSharedMemorySize, SMEM_SZ);
    dim3 gg(F_DIM / 128, M_TOK / 128);
    hybrid_dc_gemm<<<gg, 512, SMEM_SZ>>>(bias, out);
}